// round 14
// baseline (speedup 1.0000x reference)
#include <cuda_runtime.h>
#include <math.h>

#define BB 128
#define TT 512
#define ENC 512
#define HHD 512
#define AA 18
#define MM (BB*TT)
#define G4 (4*HHD)

#define N_LOGITS ((size_t)MM*AA)
#define OFF_LOGITS ((size_t)0)
#define OFF_VALUES (N_LOGITS)
#define OFF_HT (OFF_VALUES + (size_t)MM)
#define OFF_CT (OFF_HT + (size_t)BB*HHD)
#define OFF_AR (OFF_CT + (size_t)BB*HHD)
#define OFF_TAR (OFF_AR + 1)
#define NGATE ((size_t)MM*HHD)
#define OFF_IG (OFF_TAR + 1)
#define OFF_FG (OFF_IG + NGATE)
#define OFF_GG (OFF_FG + NGATE)
#define OFF_OG (OFF_GG + NGATE)

__device__ __align__(16) float g_enc1[(size_t)MM*ENC];   // enc1; later reused as LSTM out (B,T,H)
__device__ __align__(16) float g_enc2[(size_t)MM*ENC];
__device__ __align__(16) float g_xg[(size_t)MM*G4];
__device__ __align__(16) float g_h[2][BB*HHD];
#define LOSS_BLOCKS 2048
__device__ double g_part[2][LOSS_BLOCKS];
__device__ unsigned g_arriveG[4];
__device__ unsigned g_releaseG[4];

__device__ __forceinline__ void fma2(unsigned long long& d, unsigned long long a, unsigned long long b){
    asm("fma.rn.f32x2 %0, %1, %2, %0;" : "+l"(d) : "l"(a), "l"(b));
}
__device__ __forceinline__ unsigned long long f2dup(float x){
    unsigned long long r; asm("mov.b64 %0, {%1, %1};" : "=l"(r) : "r"(__float_as_uint(x))); return r;
}
__device__ __forceinline__ unsigned long long f2pack(float lo, float hi){
    unsigned long long r; asm("mov.b64 %0, {%1, %2};" : "=l"(r) : "r"(__float_as_uint(lo)), "r"(__float_as_uint(hi))); return r;
}
__device__ __forceinline__ void unpack2(unsigned long long v, float& lo, float& hi){
    unsigned l,h; asm("mov.b64 {%0, %1}, %2;" : "=r"(l), "=r"(h) : "l"(v));
    lo=__uint_as_float(l); hi=__uint_as_float(h);
}

// ================= GEMM (NT) ================= (unchanged; near FFMA2 roofline)
template<int ACT>
__global__ __launch_bounds__(256)
void gemm_nt(const float* __restrict__ A, const float* __restrict__ Bm,
             const float* __restrict__ bias1, const float* __restrict__ bias2,
             float* __restrict__ C, int K, int N, const float* hxs_init)
{
    __shared__ __align__(16) float As[2][16][132];
    __shared__ __align__(16) float Bs[2][16][132];
    const int tid = threadIdx.x;

    if (hxs_init && blockIdx.x==0 && blockIdx.y==0){
        if (tid==0){
#pragma unroll
            for (int g=0;g<4;g++){ g_arriveG[g]=0u; g_releaseG[g]=0u; }
        }
        for (int i=tid;i<BB*HHD/4;i+=256)
            ((float4*)g_h[0])[i] = ((const float4*)hxs_init)[i];
    }

    const int tx = tid & 15, ty = tid >> 4;
    const float* Ab = A + (size_t)blockIdx.y * 128 * K;
    const float* Bb = Bm + (size_t)blockIdx.x * 128 * K;

    const int row0 = tid >> 2, c4 = (tid & 3) << 2;
    const int row1 = row0 + 64;

    unsigned long long acc[4][8];
#pragma unroll
    for (int i=0;i<4;i++)
#pragma unroll
        for (int j=0;j<8;j++) acc[i][j]=0ull;

    const int nk = K >> 4;
    {
        float4 a0 = __ldcg((const float4*)(Ab + (size_t)row0*K + c4));
        float4 b0 = __ldcg((const float4*)(Bb + (size_t)row0*K + c4));
        float4 a1 = __ldcg((const float4*)(Ab + (size_t)row1*K + c4));
        float4 b1 = __ldcg((const float4*)(Bb + (size_t)row1*K + c4));
        As[0][c4+0][row0]=a0.x; As[0][c4+1][row0]=a0.y; As[0][c4+2][row0]=a0.z; As[0][c4+3][row0]=a0.w;
        Bs[0][c4+0][row0]=b0.x; Bs[0][c4+1][row0]=b0.y; Bs[0][c4+2][row0]=b0.z; Bs[0][c4+3][row0]=b0.w;
        As[0][c4+0][row1]=a1.x; As[0][c4+1][row1]=a1.y; As[0][c4+2][row1]=a1.z; As[0][c4+3][row1]=a1.w;
        Bs[0][c4+0][row1]=b1.x; Bs[0][c4+1][row1]=b1.y; Bs[0][c4+2][row1]=b1.z; Bs[0][c4+3][row1]=b1.w;
    }
    __syncthreads();

    int buf = 0;
    for (int kt=0; kt<nk; kt++){
        float4 pa0, pb0, pa1, pb1;
        const bool more = (kt+1 < nk);
        if (more){
            int k0 = (kt+1) << 4;
            pa0 = __ldcg((const float4*)(Ab + (size_t)row0*K + k0 + c4));
            pb0 = __ldcg((const float4*)(Bb + (size_t)row0*K + k0 + c4));
            pa1 = __ldcg((const float4*)(Ab + (size_t)row1*K + k0 + c4));
            pb1 = __ldcg((const float4*)(Bb + (size_t)row1*K + k0 + c4));
        }
#pragma unroll
        for (int kk=0;kk<16;kk++){
            ulonglong2 ua = *(const ulonglong2*)&As[buf][kk][ty*8];
            ulonglong2 ub = *(const ulonglong2*)&As[buf][kk][ty*8+4];
            unsigned long long ap[4] = { ua.x, ua.y, ub.x, ub.y };
            float4 f0 = *(const float4*)&Bs[buf][kk][tx*8];
            float4 f1 = *(const float4*)&Bs[buf][kk][tx*8+4];
            unsigned long long bd[8] = { f2dup(f0.x),f2dup(f0.y),f2dup(f0.z),f2dup(f0.w),
                                         f2dup(f1.x),f2dup(f1.y),f2dup(f1.z),f2dup(f1.w) };
#pragma unroll
            for (int i=0;i<4;i++)
#pragma unroll
                for (int j=0;j<8;j++) fma2(acc[i][j], ap[i], bd[j]);
        }
        if (more){
            int nb = buf ^ 1;
            As[nb][c4+0][row0]=pa0.x; As[nb][c4+1][row0]=pa0.y; As[nb][c4+2][row0]=pa0.z; As[nb][c4+3][row0]=pa0.w;
            Bs[nb][c4+0][row0]=pb0.x; Bs[nb][c4+1][row0]=pb0.y; Bs[nb][c4+2][row0]=pb0.z; Bs[nb][c4+3][row0]=pb0.w;
            As[nb][c4+0][row1]=pa1.x; As[nb][c4+1][row1]=pa1.y; As[nb][c4+2][row1]=pa1.z; As[nb][c4+3][row1]=pa1.w;
            Bs[nb][c4+0][row1]=pb1.x; Bs[nb][c4+1][row1]=pb1.y; Bs[nb][c4+2][row1]=pb1.z; Bs[nb][c4+3][row1]=pb1.w;
            __syncthreads();
            buf = nb;
        }
    }

    const int colb = blockIdx.x*128 + tx*8;
    float bv[8];
#pragma unroll
    for (int j=0;j<8;j++) bv[j] = bias1[colb+j] + (bias2 ? bias2[colb+j] : 0.f);
    const size_t rowb = (size_t)blockIdx.y*128 + ty*8;
#pragma unroll
    for (int i=0;i<4;i++){
        float v0[8], v1[8];
#pragma unroll
        for (int j=0;j<8;j++){
            float x0,x1; unpack2(acc[i][j],x0,x1);
            x0+=bv[j]; x1+=bv[j];
            if (ACT==1){ x0 = x0/(1.f+expf(-x0)); x1 = x1/(1.f+expf(-x1)); }
            v0[j]=x0; v1[j]=x1;
        }
        float* c0 = C + (rowb + 2*i)*(size_t)N + colb;
        float* c1 = c0 + N;
        __stcg((float4*)(c0),   make_float4(v0[0],v0[1],v0[2],v0[3]));
        __stcg((float4*)(c0+4), make_float4(v0[4],v0[5],v0[6],v0[7]));
        __stcg((float4*)(c1),   make_float4(v1[0],v1[1],v1[2],v1[3]));
        __stcg((float4*)(c1+4), make_float4(v1[4],v1[5],v1[6],v1[7]));
    }
}

// ================= Persistent LSTM v4: 512 threads, 16 warps =================
// 128 CTAs = 4 b-tiles(32 rows) x 32 h-tiles(16 h). 512 threads:
//   warp w (0..15): kq = w>>2 (k-quarter), hloc set = (w&3)*4 + lane>>3
//   lane: hl_in = lane>>3 (4 hloc), ks_in = lane&7; ks = kq*8+ks_in (32 slices of 16)
// Per-thread weights: 4 gates x 16 floats = 32 u64 regs. Warp LDS: 8 unique
// 16B addrs + 4-way hloc broadcast = 1 wavefront/instr (skewed stride 20).
// Reduce: 6 shuffles within 8-lane groups -> psum[idx][kq][hl] (bank-clean);
// phase2 sums 4 kq partials. Grid barrier per b-tile group (fan-in 32).
#define HROW4 640             // 512 + 4 gap per 16: pos = k + (k>>4)*4
__global__ __launch_bounds__(512, 1)
void lstm_kernel(const float* __restrict__ Whh, const float* __restrict__ cxs,
                 float* __restrict__ dout)
{
    extern __shared__ __align__(16) float smem[];
    float* hsm  = smem;                       // 32 x 640           (81,920B)
    float* xsm  = hsm + 32*HROW4;             // [32*4][17]          (8,704B)
    float* psum = xsm + 32*4*17;              // [128*4][17]        (34,816B)
    const int tid   = threadIdx.x;
    const int grp   = blockIdx.x & 3;
    const int b0    = grp * 32;
    const int hbase = (blockIdx.x >> 2) * 16;
    const int lane  = tid & 31;
    const int wid   = tid >> 5;               // 0..15
    const int kq    = wid >> 2;               // 0..3
    const int hloc  = (wid & 3)*4 + (lane >> 3);
    const int ks    = kq*8 + (lane & 7);      // 0..31 (16 floats each)

    // ---- weights: 4 gates x 16-float slice in registers (once) ----
    unsigned long long w[4][8];
#pragma unroll
    for (int g=0; g<4; g++){
        const float* wp = Whh + ((size_t)(g*HHD + hbase + hloc))*HHD + ks*16;
#pragma unroll
        for (int j=0;j<4;j++){
            float4 v = __ldg((const float4*)(wp + j*4));
            w[g][2*j]   = f2pack(v.x, v.y);
            w[g][2*j+1] = f2pack(v.z, v.w);
        }
    }

    // ---- phase2: one cell per thread ----
    const int r2 = tid >> 4, hl2 = tid & 15;   // r2 0..31
    float cc = cxs[(size_t)(b0+r2)*HHD + hbase + hl2];

    float* outb = g_enc1;
    float* gp1 = dout + OFF_IG;  float* gp2 = dout + OFF_FG;
    float* gp3 = dout + OFF_GG;  float* gp4 = dout + OFF_OG;
    unsigned* arr = &g_arriveG[grp];
    unsigned* rel = &g_releaseG[grp];

    for (int t=0;t<TT;t++){
        const float* hin = g_h[t&1];
        float* hnx = g_h[(t+1)&1];

        // poll previous step's release (all lanes; warp-broadcast load)
        if (t > 0){
            unsigned rv;
            do {
                asm volatile("ld.acquire.gpu.global.u32 %0, [%1];"
                             : "=r"(rv) : "l"(rel) : "memory");
            } while (rv < (unsigned)t);
        }

        // stage h (32x512), skew: pos = k + (k>>4)*4 ; 8 float4/thread
#pragma unroll 4
        for (int l=tid;l<4096;l+=512){
            int r = l>>7, f4 = l&127;
            float4 v = __ldcv((const float4*)(hin + (size_t)(b0+r)*HHD + f4*4));
            *(float4*)&hsm[r*HROW4 + f4*4 + (f4>>2)*4] = v;
        }
        // stage xg tile (1 float4/thread) -> xsm[(r*4+g)*17 + q]
        {
            int r = tid>>4, rem = tid&15, g = rem>>2, q = (rem&3)<<2;
            float4 v = __ldcg((const float4*)(g_xg + ((size_t)(b0+r)*TT + t)*G4 + (size_t)g*HHD + hbase + q));
            float* dst = &xsm[(r*4+g)*17 + q];
            dst[0]=v.x; dst[1]=v.y; dst[2]=v.z; dst[3]=v.w;
        }
        __syncthreads();

        // ---- phase 1: 16 chunks of 2 rows; 8 outputs (2r x 4g) per chunk ----
#pragma unroll 1
        for (int c=0;c<16;c++){
            const float* hp0 = hsm + (2*c)*HROW4 + ks*20;
            const float* hp1 = hp0 + HROW4;
            unsigned long long acc[8];
#pragma unroll
            for (int i=0;i<8;i++) acc[i]=0ull;
#pragma unroll
            for (int j=0;j<4;j++){
                ulonglong2 ha = *(const ulonglong2*)(hp0 + j*4);
                ulonglong2 hb = *(const ulonglong2*)(hp1 + j*4);
                fma2(acc[0], w[0][2*j], ha.x); fma2(acc[0], w[0][2*j+1], ha.y);
                fma2(acc[1], w[1][2*j], ha.x); fma2(acc[1], w[1][2*j+1], ha.y);
                fma2(acc[2], w[2][2*j], ha.x); fma2(acc[2], w[2][2*j+1], ha.y);
                fma2(acc[3], w[3][2*j], ha.x); fma2(acc[3], w[3][2*j+1], ha.y);
                fma2(acc[4], w[0][2*j], hb.x); fma2(acc[4], w[0][2*j+1], hb.y);
                fma2(acc[5], w[1][2*j], hb.x); fma2(acc[5], w[1][2*j+1], hb.y);
                fma2(acc[6], w[2][2*j], hb.x); fma2(acc[6], w[2][2*j+1], hb.y);
                fma2(acc[7], w[3][2*j], hb.x); fma2(acc[7], w[3][2*j+1], hb.y);
            }
            float v[8];
#pragma unroll
            for (int i=0;i<8;i++){ float lo,hi; unpack2(acc[i],lo,hi); v[i]=lo+hi; }
            // reduce-scatter over 8-lane ks_in group: output o = ks_in (bit2->row, bits1:0->gate)
            {
                int b4 = lane & 4;
#pragma unroll
                for (int i=0;i<4;i++){
                    float keep = b4 ? v[i+4] : v[i];
                    float send = b4 ? v[i]   : v[i+4];
                    v[i] = keep + __shfl_xor_sync(0xffffffffu, send, 4);
                }
                int b2 = lane & 2;
#pragma unroll
                for (int i=0;i<2;i++){
                    float keep = b2 ? v[i+2] : v[i];
                    float send = b2 ? v[i]   : v[i+2];
                    v[i] = keep + __shfl_xor_sync(0xffffffffu, send, 2);
                }
                int b1 = lane & 1;
                {
                    float keep = b1 ? v[1] : v[0];
                    float send = b1 ? v[0] : v[1];
                    v[0] = keep + __shfl_xor_sync(0xffffffffu, send, 1);
                }
            }
            // lane holds partial for idx = 8c + o over k-quarter kq
            int o = lane & 7;
            psum[((8*c + o)*4 + kq)*17 + hloc] = v[0];
        }
        __syncthreads();

        // ---- phase 2: one cell per thread (grouped reciprocals) ----
        float pre[4];
#pragma unroll
        for (int g=0; g<4; g++){
            const float* pp = psum + ((r2*4+g)*4)*17 + hl2;
            pre[g] = ((pp[0] + pp[17]) + (pp[34] + pp[51])) + xsm[(r2*4+g)*17 + hl2];
        }
        float ei = expf(-pre[0]);
        float ef = expf(-pre[1]);
        float eg = expf(-2.f*pre[2]);
        float eo = expf(-pre[3]);
        float d0 = 1.f+ei, d1 = 1.f+ef, d2 = 1.f+eg, d3 = 1.f+eo;
        float p01 = d0*d1, p23 = d2*d3;
        float rp = 1.f/(p01*p23);
        float ig = rp*d1*p23;
        float fg = rp*d0*p23;
        float gg = (1.f-eg)*(rp*p01*d3);
        float og = rp*p01*d2;
        cc = fg*cc + ig*gg;
        float ec = expf(-2.f*cc);
        float tc = (1.f-ec)/(1.f+ec);
        float ho = og*tc;
        __stcg(hnx + (size_t)(b0+r2)*HHD + hbase + hl2, ho);

        __syncthreads();   // all hnx stores issued before arrive
        if (tid==0){
            unsigned v;
            asm volatile("atom.acq_rel.gpu.global.add.u32 %0, [%1], %2;"
                         : "=r"(v) : "l"(arr), "r"(1u) : "memory");
            if (v == 31u){
                *arr = 0u;
                asm volatile("st.release.gpu.global.u32 [%0], %1;"
                             :: "l"(rel), "r"((unsigned)(t+1)) : "memory");
            }
        }

        // gate/out stores overlap the next poll
        {
            size_t base = ((size_t)(b0+r2)*TT + t)*HHD + hbase + hl2;
            __stcg(outb + base, ho);
            __stcg(gp1 + base, ig);
            __stcg(gp2 + base, fg);
            __stcg(gp3 + base, gg);
            __stcg(gp4 + base, og);
        }
        if (t==TT-1){
            dout[OFF_HT + (size_t)(b0+r2)*HHD + hbase + hl2] = ho;
            dout[OFF_CT + (size_t)(b0+r2)*HHD + hbase + hl2] = cc;
        }
    }
}

__global__ __launch_bounds__(256)
void head_kernel(const float* __restrict__ Wa, const float* __restrict__ ba,
                 const float* __restrict__ Wc, const float* __restrict__ bc,
                 float* __restrict__ dout)
{
    __shared__ __align__(16) float xsr[16][516];
    const int tid = threadIdx.x;
    const size_t m0 = (size_t)blockIdx.x * 16;
    for (int l=tid;l<2048;l+=256){
        int r=l>>7, c4=(l&127)<<2;
        *(float4*)&xsr[r][c4] = *(const float4*)(g_enc1 + (m0+r)*HHD + c4);
    }
    __syncthreads();
    for (int o=tid;o<16*19;o+=256){
        int r=o/19, n=o-r*19;
        const float* wrow = (n<18) ? (Wa + (size_t)n*HHD) : Wc;
        float acc=0.f;
#pragma unroll 4
        for (int k=0;k<HHD;k+=4){
            float4 w = __ldg((const float4*)(wrow+k));
            float4 x = *(const float4*)&xsr[r][k];
            acc += x.x*w.x + x.y*w.y + x.z*w.z + x.w*w.w;
        }
        size_t m = m0 + r;
        if (n<18) dout[OFF_LOGITS + m*AA + n] = acc + ba[n];
        else      dout[OFF_VALUES + m] = acc + bc[0];
    }
}

__global__ __launch_bounds__(256)
void loss_partial()
{
    float s1=0.f, s2=0.f;
    const size_t n = (size_t)MM*HHD;
    for (size_t i=(size_t)blockIdx.x*256+threadIdx.x; i<n; i+=(size_t)LOSS_BLOCKS*256){
        float x = g_enc1[i];
        s1 += x*x;
        unsigned t = ((unsigned)(i>>9)) & 511u;
        if (t != 511u){ float d = g_enc1[i+512] - x; s2 += d*d; }
    }
    __shared__ double r1[256], r2[256];
    r1[threadIdx.x]=(double)s1; r2[threadIdx.x]=(double)s2;
    __syncthreads();
    for (int s=128;s>0;s>>=1){
        if (threadIdx.x<s){ r1[threadIdx.x]+=r1[threadIdx.x+s]; r2[threadIdx.x]+=r2[threadIdx.x+s]; }
        __syncthreads();
    }
    if (threadIdx.x==0){ g_part[0][blockIdx.x]=r1[0]; g_part[1][blockIdx.x]=r2[0]; }
}

__global__ void loss_final(float* __restrict__ dout)
{
    __shared__ double r1[256], r2[256];
    double s1=0.0, s2=0.0;
    for (int i=threadIdx.x;i<LOSS_BLOCKS;i+=256){ s1+=g_part[0][i]; s2+=g_part[1][i]; }
    r1[threadIdx.x]=s1; r2[threadIdx.x]=s2;
    __syncthreads();
    for (int s=128;s>0;s>>=1){
        if (threadIdx.x<s){ r1[threadIdx.x]+=r1[threadIdx.x+s]; r2[threadIdx.x]+=r2[threadIdx.x+s]; }
        __syncthreads();
    }
    if (threadIdx.x==0){
        dout[OFF_AR]  = (float)(r1[0] * (0.01 / ((double)MM * HHD)));
        dout[OFF_TAR] = (float)(r2[0] * (0.01 / ((double)BB * (TT-1) * HHD)));
    }
}

extern "C" void kernel_launch(void* const* d_in, const int* in_sizes, int n_in,
                              void* d_out, int out_size)
{
    const float* obs  = (const float*)d_in[0];
    const float* hxs  = (const float*)d_in[1];
    const float* cxs  = (const float*)d_in[2];
    const float* W1   = (const float*)d_in[3];
    const float* b1   = (const float*)d_in[4];
    const float* W2   = (const float*)d_in[5];
    const float* b2   = (const float*)d_in[6];
    const float* W_ih = (const float*)d_in[7];
    const float* W_hh = (const float*)d_in[8];
    const float* b_ih = (const float*)d_in[9];
    const float* b_hh = (const float*)d_in[10];
    const float* Wa   = (const float*)d_in[11];
    const float* ba   = (const float*)d_in[12];
    const float* Wc   = (const float*)d_in[13];
    const float* bc   = (const float*)d_in[14];
    float* dout = (float*)d_out;

    float* enc1; cudaGetSymbolAddress((void**)&enc1, g_enc1);
    float* enc2; cudaGetSymbolAddress((void**)&enc2, g_enc2);
    float* xg;   cudaGetSymbolAddress((void**)&xg,   g_xg);

    const int lstm_smem = (32*HROW4 + 32*4*17 + 128*4*17) * (int)sizeof(float);
    cudaFuncSetAttribute(lstm_kernel, cudaFuncAttributeMaxDynamicSharedMemorySize, lstm_smem);

    // enc1 = silu(obs @ W1^T + b1); block(0,0) also does LSTM init
    gemm_nt<1><<<dim3(ENC/128, MM/128), 256>>>(obs, W1, b1, nullptr, enc1, 128, ENC, hxs);
    // enc2 = silu(enc1 @ W2^T + b2)
    gemm_nt<1><<<dim3(ENC/128, MM/128), 256>>>(enc1, W2, b2, nullptr, enc2, ENC, ENC, nullptr);
    // xg = enc2 @ W_ih^T + b_ih + b_hh
    gemm_nt<0><<<dim3(G4/128, MM/128), 256>>>(enc2, W_ih, b_ih, b_hh, xg, ENC, G4, nullptr);

    lstm_kernel<<<128, 512, lstm_smem>>>(W_hh, cxs, dout);   // ncu -s 5 lands here
    head_kernel<<<MM/16, 256>>>(Wa, ba, Wc, bc, dout);
    loss_partial<<<LOSS_BLOCKS, 256>>>();
    loss_final<<<1, 256>>>(dout);
}

// round 16
// speedup vs baseline: 1.1452x; 1.1452x over previous
#include <cuda_runtime.h>
#include <cuda_bf16.h>
#include <math.h>
#include <stdint.h>

#define BB 128
#define TT 512
#define OBS 128
#define ENC 512
#define HHD 512
#define AA 18
#define MM (BB*TT)
#define G4 (4*HHD)

#define N_LOGITS ((size_t)MM*AA)
#define OFF_LOGITS ((size_t)0)
#define OFF_VALUES (N_LOGITS)
#define OFF_HT (OFF_VALUES + (size_t)MM)
#define OFF_CT (OFF_HT + (size_t)BB*HHD)
#define OFF_AR (OFF_CT + (size_t)BB*HHD)
#define OFF_TAR (OFF_AR + 1)
#define NGATE ((size_t)MM*HHD)
#define OFF_IG (OFF_TAR + 1)
#define OFF_FG (OFF_IG + NGATE)
#define OFF_GG (OFF_FG + NGATE)
#define OFF_OG (OFF_GG + NGATE)

__device__ __align__(16) float g_enc1[(size_t)MM*ENC];   // LSTM out (B,T,H)
__device__ __align__(16) float g_xg[(size_t)MM*G4];
__device__ __align__(16) float g_h[2][BB*HHD];
// split-bf16 packed (lo16=hi bf16, hi16=lo bf16) activations & weights
__device__ __align__(16) uint32_t g_obsp[(size_t)MM*OBS];
__device__ __align__(16) uint32_t g_enc1p[(size_t)MM*ENC];
__device__ __align__(16) uint32_t g_enc2p[(size_t)MM*ENC];
__device__ __align__(16) uint32_t g_w1p[ENC*OBS];
__device__ __align__(16) uint32_t g_w2p[ENC*ENC];
__device__ __align__(16) uint32_t g_wihp[G4*ENC];
#define LOSS_BLOCKS 2048
__device__ double g_part[2][LOSS_BLOCKS];
__device__ unsigned g_arriveG[4];
__device__ unsigned g_releaseG[4];

__device__ __forceinline__ void fma2(unsigned long long& d, unsigned long long a, unsigned long long b){
    asm("fma.rn.f32x2 %0, %1, %2, %0;" : "+l"(d) : "l"(a), "l"(b));
}
__device__ __forceinline__ unsigned long long f2pack(float lo, float hi){
    unsigned long long r; asm("mov.b64 %0, {%1, %2};" : "=l"(r) : "r"(__float_as_uint(lo)), "r"(__float_as_uint(hi))); return r;
}
__device__ __forceinline__ void unpack2(unsigned long long v, float& lo, float& hi){
    unsigned l,h; asm("mov.b64 {%0, %1}, %2;" : "=r"(l), "=r"(h) : "l"(v));
    lo=__uint_as_float(l); hi=__uint_as_float(h);
}
__device__ __forceinline__ uint32_t packsplit(float x){
    __nv_bfloat16 h = __float2bfloat16(x);
    float r = x - __bfloat162float(h);
    __nv_bfloat16 l = __float2bfloat16(r);
    return (uint32_t)(*(uint16_t*)&h) | ((uint32_t)(*(uint16_t*)&l) << 16);
}
__device__ __forceinline__ void mma16816(float* c, const uint32_t* a, uint32_t b0, uint32_t b1){
    asm volatile("mma.sync.aligned.m16n8k16.row.col.f32.bf16.bf16.f32 "
        "{%0,%1,%2,%3}, {%4,%5,%6,%7}, {%8,%9}, {%0,%1,%2,%3};"
        : "+f"(c[0]), "+f"(c[1]), "+f"(c[2]), "+f"(c[3])
        : "r"(a[0]), "r"(a[1]), "r"(a[2]), "r"(a[3]), "r"(b0), "r"(b1));
}

// ============ pack + init ============
__global__ __launch_bounds__(256)
void conv_init(const float* __restrict__ obs, const float* __restrict__ W1,
               const float* __restrict__ W2, const float* __restrict__ Wih,
               const float* __restrict__ hxs)
{
    const size_t stride = (size_t)gridDim.x * 256;
    size_t i0 = (size_t)blockIdx.x * 256 + threadIdx.x;
    for (size_t i=i0; i<(size_t)MM*OBS; i+=stride) g_obsp[i] = packsplit(obs[i]);
    for (size_t i=i0; i<(size_t)ENC*OBS; i+=stride) g_w1p[i]  = packsplit(W1[i]);
    for (size_t i=i0; i<(size_t)ENC*ENC; i+=stride) g_w2p[i]  = packsplit(W2[i]);
    for (size_t i=i0; i<(size_t)G4*ENC;  i+=stride) g_wihp[i] = packsplit(Wih[i]);
    if (blockIdx.x==0){
        if (threadIdx.x==0){
#pragma unroll
            for (int g=0;g<4;g++){ g_arriveG[g]=0u; g_releaseG[g]=0u; }
        }
        for (int i=threadIdx.x; i<BB*HHD/4; i+=256)
            ((float4*)g_h[0])[i] = ((const float4*)hxs)[i];
    }
}

// ============ HMMA split-bf16 GEMM (NT): C = act(A@B^T + b1 (+b2)) ============
// BM=BN=128, BK=32, 256 threads (8 warps, 4x2 M-N warp grid, warp tile 32x64).
// 3 MMA passes (AhBh + AlBh + AhBl) recover fp32-level accuracy.
// Fragments loaded by plain 32-bit LDS (PTX ISA m16n8k16 layouts); stride-40
// bf16 smem rows are bank-conflict-free for the 8-group x 4-lane pattern.
template<int ACT, int OUT_PACK>
__global__ __launch_bounds__(256)
void gemm_mma(const uint32_t* __restrict__ A, const uint32_t* __restrict__ Bw,
              const float* __restrict__ bias1, const float* __restrict__ bias2,
              void* __restrict__ Cout, int K, int N)
{
    __shared__ __align__(16) __nv_bfloat16 sAh[128][40];
    __shared__ __align__(16) __nv_bfloat16 sAl[128][40];
    __shared__ __align__(16) __nv_bfloat16 sBh[128][40];
    __shared__ __align__(16) __nv_bfloat16 sBl[128][40];
    __shared__ float sbias[128];
    const int tid = threadIdx.x;
    const int lane = tid & 31, wid = tid >> 5;
    const int wm = (wid & 3) * 32, wn = (wid >> 2) * 64;
    const size_t m0 = (size_t)blockIdx.y * 128;
    const int n0 = blockIdx.x * 128;
    const int group = lane >> 2, tig = lane & 3;

    if (tid < 128) sbias[tid] = bias1[n0+tid] + (bias2 ? bias2[n0+tid] : 0.f);

    float acc[2][8][4];
#pragma unroll
    for (int i=0;i<2;i++)
#pragma unroll
        for (int j=0;j<8;j++)
#pragma unroll
            for (int q=0;q<4;q++) acc[i][j][q]=0.f;

    for (int kt = 0; kt < K; kt += 32){
        __syncthreads();   // previous compute done before restaging
        // stage A (128x32 u32) and B (128x32 u32), unpack hi/lo
        for (int idx = tid; idx < 2048; idx += 256){
            int sel = idx >> 10;
            int l = idx & 1023;
            int row = l >> 3, q = l & 7;
            const uint32_t* src = sel ? (Bw + (size_t)(n0+row)*K + kt + q*4)
                                      : (A + (m0+row)*(size_t)K + kt + q*4);
            uint4 v = __ldcg((const uint4*)src);
            uint32_t h0 = (v.x & 0xffffu) | (v.y << 16);
            uint32_t h1 = (v.z & 0xffffu) | (v.w << 16);
            uint32_t l0 = (v.x >> 16) | (v.y & 0xffff0000u);
            uint32_t l1 = (v.z >> 16) | (v.w & 0xffff0000u);
            uint32_t* dh = (uint32_t*)(sel ? &sBh[row][q*4] : &sAh[row][q*4]);
            uint32_t* dl = (uint32_t*)(sel ? &sBl[row][q*4] : &sAl[row][q*4]);
            dh[0]=h0; dh[1]=h1; dl[0]=l0; dl[1]=l1;
        }
        __syncthreads();
#pragma unroll
        for (int ks = 0; ks < 32; ks += 16){
            uint32_t ah[2][4], al[2][4];
#pragma unroll
            for (int mt=0; mt<2; mt++){
                int m = wm + mt*16 + group;
                int kc = ks + tig*2;
                ah[mt][0] = *(const uint32_t*)&sAh[m][kc];
                ah[mt][1] = *(const uint32_t*)&sAh[m+8][kc];
                ah[mt][2] = *(const uint32_t*)&sAh[m][kc+8];
                ah[mt][3] = *(const uint32_t*)&sAh[m+8][kc+8];
                al[mt][0] = *(const uint32_t*)&sAl[m][kc];
                al[mt][1] = *(const uint32_t*)&sAl[m+8][kc];
                al[mt][2] = *(const uint32_t*)&sAl[m][kc+8];
                al[mt][3] = *(const uint32_t*)&sAl[m+8][kc+8];
            }
#pragma unroll
            for (int nt=0; nt<8; nt++){
                int n = wn + nt*8 + group;
                int kc = ks + tig*2;
                uint32_t bh0 = *(const uint32_t*)&sBh[n][kc];
                uint32_t bh1 = *(const uint32_t*)&sBh[n][kc+8];
                uint32_t bl0 = *(const uint32_t*)&sBl[n][kc];
                uint32_t bl1 = *(const uint32_t*)&sBl[n][kc+8];
#pragma unroll
                for (int mt=0; mt<2; mt++){
                    mma16816(acc[mt][nt], ah[mt], bh0, bh1);
                    mma16816(acc[mt][nt], al[mt], bh0, bh1);
                    mma16816(acc[mt][nt], ah[mt], bl0, bl1);
                }
            }
        }
    }

    // epilogue: c0,c1 = row group, cols tig*2,+1 ; c2,c3 = row group+8
#pragma unroll
    for (int mt=0; mt<2; mt++){
#pragma unroll
        for (int nt=0; nt<8; nt++){
            int ncol = wn + nt*8 + tig*2;
            float b0 = sbias[ncol], b1 = sbias[ncol+1];
            size_t gm0 = m0 + wm + mt*16 + group;
            size_t gn  = (size_t)n0 + ncol;
            float x0 = acc[mt][nt][0] + b0, x1 = acc[mt][nt][1] + b1;
            float x2 = acc[mt][nt][2] + b0, x3 = acc[mt][nt][3] + b1;
            if (ACT==1){
                x0 = x0/(1.f+expf(-x0)); x1 = x1/(1.f+expf(-x1));
                x2 = x2/(1.f+expf(-x2)); x3 = x3/(1.f+expf(-x3));
            }
            if (OUT_PACK){
                uint32_t* C = (uint32_t*)Cout;
                uint2 v0 = make_uint2(packsplit(x0), packsplit(x1));
                uint2 v1 = make_uint2(packsplit(x2), packsplit(x3));
                *(uint2*)(C + gm0*(size_t)N + gn) = v0;
                *(uint2*)(C + (gm0+8)*(size_t)N + gn) = v1;
            } else {
                float* C = (float*)Cout;
                *(float2*)(C + gm0*(size_t)N + gn) = make_float2(x0, x1);
                *(float2*)(C + (gm0+8)*(size_t)N + gn) = make_float2(x2, x3);
            }
        }
    }
}

// ================= Persistent LSTM (R13 best: weights-in-regs, 256 thr) =================
#define HROW 576
__global__ __launch_bounds__(256, 1)
void lstm_kernel(const float* __restrict__ Whh, const float* __restrict__ cxs,
                 float* __restrict__ dout)
{
    extern __shared__ __align__(16) float smemf[];
    float* hsm  = smemf;
    float* xsm  = hsm + 32*HROW;
    float* pact = xsm + 32*4*17;
    const int tid   = threadIdx.x;
    const int grp   = blockIdx.x & 3;
    const int b0    = grp * 32;
    const int hbase = (blockIdx.x >> 2) * 16;
    const int hloc  = tid >> 4;
    const int ks    = tid & 15;

    unsigned long long w[4][16];
#pragma unroll
    for (int g=0; g<4; g++){
        const float* wp = Whh + ((size_t)(g*HHD + hbase + hloc))*HHD + ks*32;
#pragma unroll
        for (int j=0;j<8;j++){
            float4 v = __ldg((const float4*)(wp + j*4));
            w[g][2*j]   = f2pack(v.x, v.y);
            w[g][2*j+1] = f2pack(v.z, v.w);
        }
    }

    const int rA = tid >> 4,  hlA = tid & 15;
    const int rB = rA + 16;
    float cA = cxs[(size_t)(b0+rA)*HHD + hbase + hlA];
    float cB = cxs[(size_t)(b0+rB)*HHD + hbase + hlA];

    float* outb = g_enc1;
    float* gp1 = dout + OFF_IG;  float* gp2 = dout + OFF_FG;
    float* gp3 = dout + OFF_GG;  float* gp4 = dout + OFF_OG;
    unsigned* arr = &g_arriveG[grp];
    unsigned* rel = &g_releaseG[grp];

    for (int t=0;t<TT;t++){
        const float* hin = g_h[t&1];
        float* hnx = g_h[(t+1)&1];

#pragma unroll 4
        for (int l=tid;l<4096;l+=256){
            int r = l>>7, f4 = l&127;
            float4 v = __ldcv((const float4*)(hin + (size_t)(b0+r)*HHD + f4*4));
            *(float4*)&hsm[r*HROW + f4*4 + (f4>>3)*4] = v;
        }
#pragma unroll 2
        for (int l=tid;l<512;l+=256){
            int r = l>>4, rem = l&15, g = rem>>2, q = (rem&3)<<2;
            float4 v = __ldcg((const float4*)(g_xg + ((size_t)(b0+r)*TT + t)*G4 + (size_t)g*HHD + hbase + q));
            float* dst = &xsm[(r*4+g)*17 + q];
            dst[0]=v.x; dst[1]=v.y; dst[2]=v.z; dst[3]=v.w;
        }
        __syncthreads();

#pragma unroll 1
        for (int c=0;c<8;c++){
            const int r0 = c*4;
            unsigned long long acc[16];
#pragma unroll
            for (int i=0;i<16;i++) acc[i]=0ull;
#pragma unroll
            for (int rl=0; rl<4; rl++){
                const float* hp = &hsm[(r0+rl)*HROW + ks*36];
#pragma unroll
                for (int j=0;j<8;j++){
                    ulonglong2 hv = *(const ulonglong2*)(hp + j*4);
                    fma2(acc[rl*4+0], w[0][2*j], hv.x); fma2(acc[rl*4+0], w[0][2*j+1], hv.y);
                    fma2(acc[rl*4+1], w[1][2*j], hv.x); fma2(acc[rl*4+1], w[1][2*j+1], hv.y);
                    fma2(acc[rl*4+2], w[2][2*j], hv.x); fma2(acc[rl*4+2], w[2][2*j+1], hv.y);
                    fma2(acc[rl*4+3], w[3][2*j], hv.x); fma2(acc[rl*4+3], w[3][2*j+1], hv.y);
                }
            }
            float v[16];
#pragma unroll
            for (int i=0;i<16;i++){ float lo,hi; unpack2(acc[i],lo,hi); v[i]=lo+hi; }
            {
                int b3 = ks & 8;
#pragma unroll
                for (int i=0;i<8;i++){
                    float keep = b3 ? v[i+8] : v[i];
                    float send = b3 ? v[i]   : v[i+8];
                    v[i] = keep + __shfl_xor_sync(0xffffffffu, send, 8);
                }
                int b2 = ks & 4;
#pragma unroll
                for (int i=0;i<4;i++){
                    float keep = b2 ? v[i+4] : v[i];
                    float send = b2 ? v[i]   : v[i+4];
                    v[i] = keep + __shfl_xor_sync(0xffffffffu, send, 4);
                }
                int b1 = ks & 2;
#pragma unroll
                for (int i=0;i<2;i++){
                    float keep = b1 ? v[i+2] : v[i];
                    float send = b1 ? v[i]   : v[i+2];
                    v[i] = keep + __shfl_xor_sync(0xffffffffu, send, 2);
                }
                int bb = ks & 1;
                {
                    float keep = bb ? v[1] : v[0];
                    float send = bb ? v[0] : v[1];
                    v[0] = keep + __shfl_xor_sync(0xffffffffu, send, 1);
                }
            }
            int idx = (r0 + (ks>>2))*4 + (ks&3);
            pact[idx*17 + hloc] = v[0] + xsm[idx*17 + hloc];
        }
        __syncthreads();

        float hoA, hoB, igA,fgA,ggA,ogA, igB,fgB,ggB,ogB;
#pragma unroll
        for (int cell=0; cell<2; cell++){
            int r  = cell ? rB : rA;
            float pre[4];
#pragma unroll
            for (int g=0; g<4; g++) pre[g] = pact[(r*4+g)*17 + hlA];
            float ei = expf(-pre[0]);
            float ef = expf(-pre[1]);
            float eg = expf(-2.f*pre[2]);
            float eo = expf(-pre[3]);
            float d0 = 1.f+ei, d1 = 1.f+ef, d2 = 1.f+eg, d3 = 1.f+eo;
            float p01 = d0*d1, p23 = d2*d3;
            float rp = 1.f/(p01*p23);
            float ig = rp*d1*p23;
            float fg = rp*d0*p23;
            float gg = (1.f-eg)*(rp*p01*d3);
            float og = rp*p01*d2;
            float cc = cell ? cB : cA;
            cc = fg*cc + ig*gg;
            float ec = expf(-2.f*cc);
            float tc = (1.f-ec)/(1.f+ec);
            float ho = og*tc;
            if (cell){ cB=cc; hoB=ho; igB=ig; fgB=fg; ggB=gg; ogB=og; }
            else     { cA=cc; hoA=ho; igA=ig; fgA=fg; ggA=gg; ogA=og; }
            __stcg(hnx + (size_t)(b0+r)*HHD + hbase + hlA, ho);
        }

        __syncthreads();
        if (tid==0){
            unsigned v;
            asm volatile("atom.release.gpu.global.add.u32 %0, [%1], %2;"
                         : "=r"(v) : "l"(arr), "r"(1u) : "memory");
            if (v == 31u){
                *arr = 0u;
                asm volatile("st.release.gpu.global.u32 [%0], %1;"
                             :: "l"(rel), "r"((unsigned)(t+1)) : "memory");
            }
        }
        {
            size_t baseA = ((size_t)(b0+rA)*TT + t)*HHD + hbase + hlA;
            size_t baseB = ((size_t)(b0+rB)*TT + t)*HHD + hbase + hlA;
            __stcg(outb + baseA, hoA);  __stcg(outb + baseB, hoB);
            __stcg(gp1 + baseA, igA);   __stcg(gp1 + baseB, igB);
            __stcg(gp2 + baseA, fgA);   __stcg(gp2 + baseB, fgB);
            __stcg(gp3 + baseA, ggA);   __stcg(gp3 + baseB, ggB);
            __stcg(gp4 + baseA, ogA);   __stcg(gp4 + baseB, ogB);
        }
        if (t==TT-1){
            dout[OFF_HT + (size_t)(b0+rA)*HHD + hbase + hlA] = hoA;
            dout[OFF_HT + (size_t)(b0+rB)*HHD + hbase + hlA] = hoB;
            dout[OFF_CT + (size_t)(b0+rA)*HHD + hbase + hlA] = cA;
            dout[OFF_CT + (size_t)(b0+rB)*HHD + hbase + hlA] = cB;
        }
        if (tid==0){
            unsigned r;
            do {
                asm volatile("ld.acquire.gpu.global.u32 %0, [%1];"
                             : "=r"(r) : "l"(rel) : "memory");
            } while (r < (unsigned)(t+1));
        }
        __syncthreads();
    }
}

__global__ __launch_bounds__(256)
void head_kernel(const float* __restrict__ Wa, const float* __restrict__ ba,
                 const float* __restrict__ Wc, const float* __restrict__ bc,
                 float* __restrict__ dout)
{
    __shared__ __align__(16) float xsr[16][516];
    const int tid = threadIdx.x;
    const size_t m0 = (size_t)blockIdx.x * 16;
    for (int l=tid;l<2048;l+=256){
        int r=l>>7, c4=(l&127)<<2;
        *(float4*)&xsr[r][c4] = *(const float4*)(g_enc1 + (m0+r)*HHD + c4);
    }
    __syncthreads();
    for (int o=tid;o<16*19;o+=256){
        int r=o/19, n=o-r*19;
        const float* wrow = (n<18) ? (Wa + (size_t)n*HHD) : Wc;
        float acc=0.f;
#pragma unroll 4
        for (int k=0;k<HHD;k+=4){
            float4 w = __ldg((const float4*)(wrow+k));
            float4 x = *(const float4*)&xsr[r][k];
            acc += x.x*w.x + x.y*w.y + x.z*w.z + x.w*w.w;
        }
        size_t m = m0 + r;
        if (n<18) dout[OFF_LOGITS + m*AA + n] = acc + ba[n];
        else      dout[OFF_VALUES + m] = acc + bc[0];
    }
}

__global__ __launch_bounds__(256)
void loss_partial()
{
    float s1=0.f, s2=0.f;
    const size_t n = (size_t)MM*HHD;
    for (size_t i=(size_t)blockIdx.x*256+threadIdx.x; i<n; i+=(size_t)LOSS_BLOCKS*256){
        float x = g_enc1[i];
        s1 += x*x;
        unsigned t = ((unsigned)(i>>9)) & 511u;
        if (t != 511u){ float d = g_enc1[i+512] - x; s2 += d*d; }
    }
    __shared__ double r1[256], r2[256];
    r1[threadIdx.x]=(double)s1; r2[threadIdx.x]=(double)s2;
    __syncthreads();
    for (int s=128;s>0;s>>=1){
        if (threadIdx.x<s){ r1[threadIdx.x]+=r1[threadIdx.x+s]; r2[threadIdx.x]+=r2[threadIdx.x+s]; }
        __syncthreads();
    }
    if (threadIdx.x==0){ g_part[0][blockIdx.x]=r1[0]; g_part[1][blockIdx.x]=r2[0]; }
}

__global__ void loss_final(float* __restrict__ dout)
{
    __shared__ double r1[256], r2[256];
    double s1=0.0, s2=0.0;
    for (int i=threadIdx.x;i<LOSS_BLOCKS;i+=256){ s1+=g_part[0][i]; s2+=g_part[1][i]; }
    r1[threadIdx.x]=s1; r2[threadIdx.x]=s2;
    __syncthreads();
    for (int s=128;s>0;s>>=1){
        if (threadIdx.x<s){ r1[threadIdx.x]+=r1[threadIdx.x+s]; r2[threadIdx.x]+=r2[threadIdx.x+s]; }
        __syncthreads();
    }
    if (threadIdx.x==0){
        dout[OFF_AR]  = (float)(r1[0] * (0.01 / ((double)MM * HHD)));
        dout[OFF_TAR] = (float)(r2[0] * (0.01 / ((double)BB * (TT-1) * HHD)));
    }
}

extern "C" void kernel_launch(void* const* d_in, const int* in_sizes, int n_in,
                              void* d_out, int out_size)
{
    const float* obs  = (const float*)d_in[0];
    const float* hxs  = (const float*)d_in[1];
    const float* cxs  = (const float*)d_in[2];
    const float* W1   = (const float*)d_in[3];
    const float* b1   = (const float*)d_in[4];
    const float* W2   = (const float*)d_in[5];
    const float* b2   = (const float*)d_in[6];
    const float* W_ih = (const float*)d_in[7];
    const float* W_hh = (const float*)d_in[8];
    const float* b_ih = (const float*)d_in[9];
    const float* b_hh = (const float*)d_in[10];
    const float* Wa   = (const float*)d_in[11];
    const float* ba   = (const float*)d_in[12];
    const float* Wc   = (const float*)d_in[13];
    const float* bc   = (const float*)d_in[14];
    float* dout = (float*)d_out;

    uint32_t *obsp, *w1p, *w2p, *wihp, *e1p, *e2p;
    cudaGetSymbolAddress((void**)&obsp, g_obsp);
    cudaGetSymbolAddress((void**)&w1p,  g_w1p);
    cudaGetSymbolAddress((void**)&w2p,  g_w2p);
    cudaGetSymbolAddress((void**)&wihp, g_wihp);
    cudaGetSymbolAddress((void**)&e1p,  g_enc1p);
    cudaGetSymbolAddress((void**)&e2p,  g_enc2p);
    float* xg; cudaGetSymbolAddress((void**)&xg, g_xg);

    const int lstm_smem = (32*HROW + 32*4*17 + 32*4*17) * (int)sizeof(float);
    cudaFuncSetAttribute(lstm_kernel, cudaFuncAttributeMaxDynamicSharedMemorySize, lstm_smem);

    conv_init<<<2048, 256>>>(obs, W1, W2, W_ih, hxs);
    // enc1p = split(silu(obs @ W1^T + b1))
    gemm_mma<1,1><<<dim3(ENC/128, MM/128), 256>>>(obsp, w1p, b1, nullptr, e1p, OBS, ENC);
    // enc2p = split(silu(enc1 @ W2^T + b2))
    gemm_mma<1,1><<<dim3(ENC/128, MM/128), 256>>>(e1p, w2p, b2, nullptr, e2p, ENC, ENC);
    // xg (fp32) = enc2 @ W_ih^T + b_ih + b_hh
    gemm_mma<0,0><<<dim3(G4/128, MM/128), 256>>>(e2p, wihp, b_ih, b_hh, xg, ENC, G4);

    lstm_kernel<<<128, 256, lstm_smem>>>(W_hh, cxs, dout);
    head_kernel<<<MM/16, 256>>>(Wa, ba, Wc, bc, dout);
    loss_partial<<<LOSS_BLOCKS, 256>>>();
    loss_final<<<1, 256>>>(dout);
}